// round 12
// baseline (speedup 1.0000x reference)
#include <cuda_runtime.h>
#include <cuda_bf16.h>

#define BQ 8
#define NQ 8192
#define MK 2048
#define CC 256
#define EPSW 1e-8f
#define GRID 8               // 8x8x8 cells
#define NCELL (GRID*GRID*GRID)
#define CELLH 0.125f

// Scratch: binned points (x,y,z,bitcast(idx)) + cell start offsets
__device__ float4 g_pts[BQ * MK];
__device__ int    g_cellstart[BQ][NCELL + 1];

// Compact per-query result: (w0, w1, bitcast(i0 | i1<<16), bitcast(i2))
__device__ float4 g_wp[BQ * NQ];

typedef unsigned long long u64t;
__device__ __forceinline__ u64t fma2(u64t a, u64t b, u64t c) {
    u64t d; asm("fma.rn.f32x2 %0, %1, %2, %3;" : "=l"(d) : "l"(a), "l"(b), "l"(c));
    return d;
}
__device__ __forceinline__ u64t mul2(u64t a, u64t b) {
    u64t d; asm("mul.rn.f32x2 %0, %1, %2;" : "=l"(d) : "l"(a), "l"(b));
    return d;
}
__device__ __forceinline__ u64t pack2(float lo, float hi) {
    u64t d; asm("mov.b64 %0, {%1, %2};" : "=l"(d) : "f"(lo), "f"(hi));
    return d;
}
__device__ __forceinline__ void unpack2(u64t v, float& lo, float& hi) {
    asm("mov.b64 {%0, %1}, %2;" : "=f"(lo), "=f"(hi) : "l"(v));
}

__device__ __forceinline__ int cell_of(float x, float y, float z) {
    int cx = min(GRID - 1, max(0, (int)(x * (float)GRID)));
    int cy = min(GRID - 1, max(0, (int)(y * (float)GRID)));
    int cz = min(GRID - 1, max(0, (int)(z * (float)GRID)));
    return (cz * GRID + cy) * GRID + cx;
}

// ---------------------------------------------------------------------------
// Kernel A: bin known points into the 8^3 grid (counting sort).
// One block per batch, 256 threads, 8 points/thread.
// ---------------------------------------------------------------------------
__global__ void __launch_bounds__(256) bin_kernel(
    const float* __restrict__ known)     // (B, M, 3)
{
    __shared__ int hist[NCELL];
    __shared__ int startsh[NCELL];
    __shared__ int wsum[8];

    const int b = blockIdx.x;
    const int t = threadIdx.x;

    hist[t] = 0; hist[t + 256] = 0;
    __syncthreads();

    const float* kb = known + (size_t)b * MK * 3;
#pragma unroll
    for (int k = 0; k < 8; k++) {
        int m = k * 256 + t;
        float x = kb[m * 3 + 0], y = kb[m * 3 + 1], z = kb[m * 3 + 2];
        atomicAdd(&hist[cell_of(x, y, z)], 1);
    }
    __syncthreads();

    // exclusive scan of hist[512]: each thread owns elements 2t, 2t+1
    int e0 = hist[2 * t], e1 = hist[2 * t + 1];
    int ps = e0 + e1;
    unsigned lane = t & 31;
    int warp = t >> 5;
    int v = ps;
#pragma unroll
    for (int off = 1; off < 32; off <<= 1) {
        int u = __shfl_up_sync(0xFFFFFFFFu, v, off);
        if (lane >= off) v += u;
    }
    if (lane == 31) wsum[warp] = v;
    __syncthreads();
    if (t < 8) {
        int w = wsum[t];
        int vv = w;
#pragma unroll
        for (int off = 1; off < 8; off <<= 1) {
            int u = __shfl_up_sync(0x000000FFu, vv, off);
            if ((int)t >= off) vv += u;
        }
        wsum[t] = vv - w;   // exclusive warp base
    }
    __syncthreads();
    int base = wsum[warp] + (v - ps);   // exclusive start for element 2t
    startsh[2 * t] = base;
    startsh[2 * t + 1] = base + e0;
    __syncthreads();

    g_cellstart[b][2 * t] = startsh[2 * t];
    g_cellstart[b][2 * t + 1] = startsh[2 * t + 1];
    if (t == 0) g_cellstart[b][NCELL] = MK;

    // reuse hist as scatter cursor
    hist[2 * t] = startsh[2 * t];
    hist[2 * t + 1] = startsh[2 * t + 1];
    __syncthreads();

#pragma unroll
    for (int k = 0; k < 8; k++) {
        int m = k * 256 + t;
        float x = kb[m * 3 + 0], y = kb[m * 3 + 1], z = kb[m * 3 + 2];
        int c = cell_of(x, y, z);
        int pos = atomicAdd(&hist[c], 1);
        g_pts[(size_t)b * MK + pos] = make_float4(x, y, z, __int_as_float(m));
    }
}

// ---------------------------------------------------------------------------
// Kernel B: three_nn via grid search. EXACT d^2, lexicographic (d2, idx)
// insert (order-independent; reproduces jax lower-index tie-break).
// Correctness guarantee: after all cells with Chebyshev radius <= r are
// processed, unprocessed points are >= r*CELLH away, so stop when
// d3^2 <= (r*CELLH)^2. Radius up to 7 covers the whole grid.
// Block 128, 1 query/thread, grid (NQ/128, BQ).
// ---------------------------------------------------------------------------
__global__ void __launch_bounds__(128) nn_kernel(
    const float* __restrict__ unknown)   // (B, N, 3)
{
    __shared__ float4 spts[MK];          // 32 KB (binned points)
    __shared__ int    sstart[NCELL + 1];

    const int b = blockIdx.y;
    for (int i = threadIdx.x; i < MK; i += 128)
        spts[i] = g_pts[(size_t)b * MK + i];
    for (int i = threadIdx.x; i < NCELL + 1; i += 128)
        sstart[i] = g_cellstart[b][i];
    __syncthreads();

    const int n = blockIdx.x * 128 + threadIdx.x;
    const float* u = unknown + ((size_t)b * NQ + n) * 3;
    const float ux = u[0], uy = u[1], uz = u[2];
    const int cx = min(GRID - 1, max(0, (int)(ux * (float)GRID)));
    const int cy = min(GRID - 1, max(0, (int)(uy * (float)GRID)));
    const int cz = min(GRID - 1, max(0, (int)(uz * (float)GRID)));

    float d0 = 1e30f, d1 = 1e30f, d2v = 1e30f;
    int   i0 = 0x7FFFFFFF, i1 = 0x7FFFFFFF, i2 = 0x7FFFFFFF;

    auto process_cell = [&](int c) {
        int s = sstart[c], e = sstart[c + 1];
        for (int p = s; p < e; p++) {
            float4 P = spts[p];
            float dx = P.x - ux, dy = P.y - uy, dz = P.z - uz;
            float d2 = fmaf(dx, dx, fmaf(dy, dy, dz * dz));
            int m = __float_as_int(P.w);
            // lexicographic (d2, idx) insert — order-independent
            bool c0 = (d2 < d0) || (d2 == d0 && m < i0);
            bool c1 = (d2 < d1) || (d2 == d1 && m < i1);
            bool c2 = (d2 < d2v) || (d2 == d2v && m < i2);
            float t0 = c0 ? d2 : d0;
            float t1 = c0 ? d0 : (c1 ? d2 : d1);
            float t2 = c1 ? d1 : (c2 ? d2 : d2v);
            int   j0 = c0 ? m  : i0;
            int   j1 = c0 ? i0 : (c1 ? m  : i1);
            int   j2 = c1 ? i1 : (c2 ? m  : i2);
            d0 = t0; d1 = t1; d2v = t2;
            i0 = j0; i1 = j1; i2 = j2;
        }
    };

    // radius-1 cube (covers the vast majority of queries)
    {
        int zlo = max(cz - 1, 0), zhi = min(cz + 1, GRID - 1);
        int ylo = max(cy - 1, 0), yhi = min(cy + 1, GRID - 1);
        int xlo = max(cx - 1, 0), xhi = min(cx + 1, GRID - 1);
        for (int z = zlo; z <= zhi; z++)
            for (int y = ylo; y <= yhi; y++)
                for (int x = xlo; x <= xhi; x++)
                    process_cell((z * GRID + y) * GRID + x);
    }

    // expanding Chebyshev shells until guaranteed
#pragma unroll 1
    for (int s = 2; s <= GRID - 1; s++) {
        float thr = CELLH * (float)(s - 1);
        if (d2v <= thr * thr) break;
        int zlo = max(cz - s, 0), zhi = min(cz + s, GRID - 1);
        int ylo = max(cy - s, 0), yhi = min(cy + s, GRID - 1);
        int xlo = max(cx - s, 0), xhi = min(cx + s, GRID - 1);
        for (int z = zlo; z <= zhi; z++)
            for (int y = ylo; y <= yhi; y++)
                for (int x = xlo; x <= xhi; x++) {
                    int ch = max(abs(z - cz), max(abs(y - cy), abs(x - cx)));
                    if (ch != s) continue;
                    process_cell((z * GRID + y) * GRID + x);
                }
    }

    const float r0 = 1.0f / (d0 + EPSW);
    const float r1 = 1.0f / (d1 + EPSW);
    const float r2 = 1.0f / (d2v + EPSW);
    const float s  = 1.0f / (r0 + r1 + r2);
    g_wp[(size_t)b * NQ + n] =
        make_float4(r0 * s, r1 * s,
                    __int_as_float(i0 | (i1 << 16)),
                    __int_as_float(i2));
}

// ---------------------------------------------------------------------------
// Kernel C: three_interpolate (unchanged — measured local floor ~33.5 us).
// ---------------------------------------------------------------------------
#define CG 4

__global__ void __launch_bounds__(256) interp_kernel(
    const float* __restrict__ feats,     // (B, C, M)
    float* __restrict__ out)             // (B, C, N)
{
    __shared__ float rowsT[MK * CG];     // 32 KB

    const int b  = blockIdx.y;
    const int c0 = blockIdx.x * CG;

    {
        const float* fp = feats + ((size_t)b * CC + c0) * MK;
#pragma unroll
        for (int it = 0; it < MK / 256; it++) {
            const int m = it * 256 + threadIdx.x;
            float a  = fp[m];
            float bb = fp[MK + m];
            float c  = fp[2 * MK + m];
            float d  = fp[3 * MK + m];
            *(float4*)&rowsT[m * 4] = make_float4(a, bb, c, d);
        }
    }
    __syncthreads();

    const float4* wp = (const float4*)&g_wp[(size_t)b * NQ];
    float* outp = out + ((size_t)b * CC + c0) * NQ;

    for (int it = 0; it < NQ / 1024; it++) {   // 8 iters
        const int n0 = it * 1024 + threadIdx.x * 4;

        float4 W0 = wp[n0 + 0];
        float4 W1 = wp[n0 + 1];
        float4 W2 = wp[n0 + 2];
        float4 W3 = wp[n0 + 3];

        int j[12];
        {
            unsigned pk0 = __float_as_uint(W0.z);
            unsigned pk1 = __float_as_uint(W1.z);
            unsigned pk2 = __float_as_uint(W2.z);
            unsigned pk3 = __float_as_uint(W3.z);
            j[0]  = pk0 & 0xFFFF; j[1]  = pk0 >> 16; j[2]  = __float_as_uint(W0.w);
            j[3]  = pk1 & 0xFFFF; j[4]  = pk1 >> 16; j[5]  = __float_as_uint(W1.w);
            j[6]  = pk2 & 0xFFFF; j[7]  = pk2 >> 16; j[8]  = __float_as_uint(W2.w);
            j[9]  = pk3 & 0xFFFF; j[10] = pk3 >> 16; j[11] = __float_as_uint(W3.w);
        }

        ulonglong2 f[12];
#pragma unroll
        for (int t = 0; t < 12; t++)
            f[t] = *(const ulonglong2*)&rowsT[j[t] * 4];

        float vq[4][4];
        const float4 Wv[4] = { W0, W1, W2, W3 };
#pragma unroll
        for (int q = 0; q < 4; q++) {
            float w0 = Wv[q].x, w1 = Wv[q].y;
            float w2 = 1.0f - w0 - w1;
            u64t w0p = pack2(w0, w0);
            u64t w1p = pack2(w1, w1);
            u64t w2p = pack2(w2, w2);
            u64t lo = fma2(w0p, f[3*q].x, fma2(w1p, f[3*q+1].x, mul2(w2p, f[3*q+2].x)));
            u64t hi = fma2(w0p, f[3*q].y, fma2(w1p, f[3*q+1].y, mul2(w2p, f[3*q+2].y)));
            unpack2(lo, vq[q][0], vq[q][1]);
            unpack2(hi, vq[q][2], vq[q][3]);
        }

#pragma unroll
        for (int c = 0; c < CG; c++) {
            float4 v = make_float4(vq[0][c], vq[1][c], vq[2][c], vq[3][c]);
            *(float4*)(outp + (size_t)c * NQ + n0) = v;
        }
    }
}

// ---------------------------------------------------------------------------
// Launch
// ---------------------------------------------------------------------------
extern "C" void kernel_launch(void* const* d_in, const int* in_sizes, int n_in,
                              void* d_out, int out_size)
{
    const float* unknown = (const float*)d_in[0];   // (8, 8192, 3)
    const float* known   = (const float*)d_in[1];   // (8, 2048, 3)
    const float* feats   = (const float*)d_in[2];   // (8, 256, 2048)
    float* out = (float*)d_out;                     // (8, 256, 8192)

    bin_kernel<<<BQ, 256>>>(known);

    dim3 g1(NQ / 128, BQ);
    nn_kernel<<<g1, 128>>>(unknown);

    dim3 g2(CC / CG, BQ);
    interp_kernel<<<g2, 256>>>(feats, out);
}

// round 13
// speedup vs baseline: 1.1302x; 1.1302x over previous
#include <cuda_runtime.h>
#include <cuda_bf16.h>

#define BQ 8
#define NQ 8192
#define MK 2048
#define CC 256
#define EPSW 1e-8f
#define GRID 8
#define NCELL (GRID*GRID*GRID)   // 512
#define CELLH 0.125f

// Scratch
__device__ float4 g_pts[BQ * MK];              // binned known points (x,y,z,idx)
__device__ int    g_cellstart[BQ][NCELL + 1];  // known-point cell offsets
__device__ int    g_qidx[BQ * NQ];             // query indices sorted by cell
__device__ int    g_qstart[BQ][NCELL + 1];     // query cell offsets
__device__ float4 g_wp[BQ * NQ];               // (w0,w1,i0|i1<<16,i2)

typedef unsigned long long u64t;
__device__ __forceinline__ u64t fma2(u64t a, u64t b, u64t c) {
    u64t d; asm("fma.rn.f32x2 %0, %1, %2, %3;" : "=l"(d) : "l"(a), "l"(b), "l"(c));
    return d;
}
__device__ __forceinline__ u64t mul2(u64t a, u64t b) {
    u64t d; asm("mul.rn.f32x2 %0, %1, %2;" : "=l"(d) : "l"(a), "l"(b));
    return d;
}
__device__ __forceinline__ u64t pack2(float lo, float hi) {
    u64t d; asm("mov.b64 %0, {%1, %2};" : "=l"(d) : "f"(lo), "f"(hi));
    return d;
}
__device__ __forceinline__ void unpack2(u64t v, float& lo, float& hi) {
    asm("mov.b64 {%0, %1}, %2;" : "=f"(lo), "=f"(hi) : "l"(v));
}

__device__ __forceinline__ int cell_of(float x, float y, float z) {
    int cx = min(GRID - 1, max(0, (int)(x * (float)GRID)));
    int cy = min(GRID - 1, max(0, (int)(y * (float)GRID)));
    int cz = min(GRID - 1, max(0, (int)(z * (float)GRID)));
    return (cz * GRID + cy) * GRID + cx;
}

// ---------------------------------------------------------------------------
// Kernel A: fused counting sort. blockIdx.y = role (0: known pts, 1: queries),
// blockIdx.x = batch. 512 threads; 512-cell histogram, block-wide scan,
// atomic-cursor scatter. Scatter order within a cell is nondeterministic,
// which is safe because the NN insert is lexicographic (order-independent).
// ---------------------------------------------------------------------------
__global__ void __launch_bounds__(512) bin_kernel(
    const float* __restrict__ known,     // (B, M, 3)
    const float* __restrict__ unknown)   // (B, N, 3)
{
    __shared__ int hist[NCELL];
    __shared__ int wsum[16];

    const int b = blockIdx.x;
    const int role = blockIdx.y;
    const int t = threadIdx.x;
    const int lane = t & 31, warp = t >> 5;

    hist[t] = 0;
    __syncthreads();

    if (role == 0) {
        const float* kb = known + (size_t)b * MK * 3;
#pragma unroll
        for (int k = 0; k < MK / 512; k++) {
            int m = k * 512 + t;
            atomicAdd(&hist[cell_of(kb[m*3], kb[m*3+1], kb[m*3+2])], 1);
        }
    } else {
        const float* ub = unknown + (size_t)b * NQ * 3;
#pragma unroll
        for (int k = 0; k < NQ / 512; k++) {
            int m = k * 512 + t;
            atomicAdd(&hist[cell_of(ub[m*3], ub[m*3+1], ub[m*3+2])], 1);
        }
    }
    __syncthreads();

    // block-wide exclusive scan of hist[512]
    int v = hist[t];
    int incl = v;
#pragma unroll
    for (int off = 1; off < 32; off <<= 1) {
        int u = __shfl_up_sync(0xFFFFFFFFu, incl, off);
        if (lane >= off) incl += u;
    }
    if (lane == 31) wsum[warp] = incl;
    __syncthreads();
    if (t < 16) {
        int w = wsum[t];
        int vv = w;
#pragma unroll
        for (int off = 1; off < 16; off <<= 1) {
            int u = __shfl_up_sync(0x0000FFFFu, vv, off);
            if (t >= off) vv += u;
        }
        wsum[t] = vv - w;   // exclusive base per warp
    }
    __syncthreads();
    int excl = wsum[warp] + incl - v;

    if (role == 0) {
        g_cellstart[b][t] = excl;
        if (t == 0) g_cellstart[b][NCELL] = MK;
    } else {
        g_qstart[b][t] = excl;
        if (t == 0) g_qstart[b][NCELL] = NQ;
    }
    __syncthreads();
    hist[t] = excl;          // reuse as scatter cursor
    __syncthreads();

    if (role == 0) {
        const float* kb = known + (size_t)b * MK * 3;
#pragma unroll
        for (int k = 0; k < MK / 512; k++) {
            int m = k * 512 + t;
            float x = kb[m*3], y = kb[m*3+1], z = kb[m*3+2];
            int pos = atomicAdd(&hist[cell_of(x, y, z)], 1);
            g_pts[(size_t)b * MK + pos] = make_float4(x, y, z, __int_as_float(m));
        }
    } else {
        const float* ub = unknown + (size_t)b * NQ * 3;
#pragma unroll
        for (int k = 0; k < NQ / 512; k++) {
            int m = k * 512 + t;
            int pos = atomicAdd(&hist[cell_of(ub[m*3], ub[m*3+1], ub[m*3+2])], 1);
            g_qidx[(size_t)b * NQ + pos] = m;
        }
    }
}

// ---------------------------------------------------------------------------
// Kernel B: three_nn, cell-coherent. One warp per cell: all 32 lanes share
// the cell -> warp-uniform shell loops, broadcast (conflict-free) LDS of
// candidate points. EXACT d^2; lexicographic (d2, idx) insert (proven
// order-independent, reproduces jax lower-index tie-break). Stop when all
// lanes' d3^2 <= ((s-1)*CELLH)^2 before shell s.
// Block 128 (4 warps = 4 cells), grid (NCELL/4, BQ) = 1024 blocks.
// ---------------------------------------------------------------------------
__global__ void __launch_bounds__(128) nn_kernel(
    const float* __restrict__ unknown)   // (B, N, 3)
{
    __shared__ float4 spts[MK];          // 32 KB
    __shared__ int    sstart[NCELL + 1];

    const int b = blockIdx.y;
    for (int i = threadIdx.x; i < MK; i += 128)
        spts[i] = g_pts[(size_t)b * MK + i];
    for (int i = threadIdx.x; i < NCELL + 1; i += 128)
        sstart[i] = g_cellstart[b][i];
    __syncthreads();

    const int wid = threadIdx.x >> 5;
    const int lane = threadIdx.x & 31;
    const int c = blockIdx.x * 4 + wid;
    const int cx = c & 7, cy = (c >> 3) & 7, cz = c >> 6;

    const int qs = g_qstart[b][c];
    const int qe = g_qstart[b][c + 1];

    for (int q0 = qs; q0 < qe; q0 += 32) {
        const int qi = q0 + lane;
        const bool act = qi < qe;
        const int n = g_qidx[(size_t)b * NQ + (act ? qi : qs)];
        const float* u = unknown + ((size_t)b * NQ + n) * 3;
        const float ux = u[0], uy = u[1], uz = u[2];

        float d0 = 1e30f, d1 = 1e30f, d2v = 1e30f;
        int   i0 = 0x7FFFFFFF, i1 = 0x7FFFFFFF, i2 = 0x7FFFFFFF;

        auto process_cell = [&](int cc) {
            int s = sstart[cc], e = sstart[cc + 1];
            for (int p = s; p < e; p++) {
                float4 P = spts[p];          // broadcast across the warp
                float dx = P.x - ux, dy = P.y - uy, dz = P.z - uz;
                float d2 = fmaf(dx, dx, fmaf(dy, dy, dz * dz));
                int m = __float_as_int(P.w);
                bool c0 = (d2 < d0) || (d2 == d0 && m < i0);
                bool c1 = (d2 < d1) || (d2 == d1 && m < i1);
                bool c2 = (d2 < d2v) || (d2 == d2v && m < i2);
                float t0 = c0 ? d2 : d0;
                float t1 = c0 ? d0 : (c1 ? d2 : d1);
                float t2 = c1 ? d1 : (c2 ? d2 : d2v);
                int   j0 = c0 ? m  : i0;
                int   j1 = c0 ? i0 : (c1 ? m  : i1);
                int   j2 = c1 ? i1 : (c2 ? m  : i2);
                d0 = t0; d1 = t1; d2v = t2;
                i0 = j0; i1 = j1; i2 = j2;
            }
        };

        // radius-1 cube (warp-uniform bounds)
        {
            int zlo = max(cz - 1, 0), zhi = min(cz + 1, GRID - 1);
            int ylo = max(cy - 1, 0), yhi = min(cy + 1, GRID - 1);
            int xlo = max(cx - 1, 0), xhi = min(cx + 1, GRID - 1);
            for (int z = zlo; z <= zhi; z++)
                for (int y = ylo; y <= yhi; y++)
                    for (int x = xlo; x <= xhi; x++)
                        process_cell((z * GRID + y) * GRID + x);
        }

        // expanding shells until every lane is provably done
#pragma unroll 1
        for (int s2 = 2; s2 <= GRID - 1; s2++) {
            float thr = CELLH * (float)(s2 - 1);
            bool need = act && (d2v > thr * thr);
            if (!__any_sync(0xFFFFFFFFu, need)) break;
            int zlo = max(cz - s2, 0), zhi = min(cz + s2, GRID - 1);
            int ylo = max(cy - s2, 0), yhi = min(cy + s2, GRID - 1);
            int xlo = max(cx - s2, 0), xhi = min(cx + s2, GRID - 1);
            for (int z = zlo; z <= zhi; z++)
                for (int y = ylo; y <= yhi; y++)
                    for (int x = xlo; x <= xhi; x++) {
                        int ch = max(abs(z - cz), max(abs(y - cy), abs(x - cx)));
                        if (ch != s2) continue;
                        process_cell((z * GRID + y) * GRID + x);
                    }
        }

        if (act) {
            const float r0 = 1.0f / (d0 + EPSW);
            const float r1 = 1.0f / (d1 + EPSW);
            const float r2 = 1.0f / (d2v + EPSW);
            const float s  = 1.0f / (r0 + r1 + r2);
            g_wp[(size_t)b * NQ + n] =
                make_float4(r0 * s, r1 * s,
                            __int_as_float(i0 | (i1 << 16)),
                            __int_as_float(i2));
        }
    }
}

// ---------------------------------------------------------------------------
// Kernel C: three_interpolate (unchanged — measured local floor ~33.5 us).
// ---------------------------------------------------------------------------
#define CG 4

__global__ void __launch_bounds__(256) interp_kernel(
    const float* __restrict__ feats,     // (B, C, M)
    float* __restrict__ out)             // (B, C, N)
{
    __shared__ float rowsT[MK * CG];     // 32 KB

    const int b  = blockIdx.y;
    const int c0 = blockIdx.x * CG;

    {
        const float* fp = feats + ((size_t)b * CC + c0) * MK;
#pragma unroll
        for (int it = 0; it < MK / 256; it++) {
            const int m = it * 256 + threadIdx.x;
            float a  = fp[m];
            float bb = fp[MK + m];
            float c  = fp[2 * MK + m];
            float d  = fp[3 * MK + m];
            *(float4*)&rowsT[m * 4] = make_float4(a, bb, c, d);
        }
    }
    __syncthreads();

    const float4* wp = (const float4*)&g_wp[(size_t)b * NQ];
    float* outp = out + ((size_t)b * CC + c0) * NQ;

    for (int it = 0; it < NQ / 1024; it++) {   // 8 iters
        const int n0 = it * 1024 + threadIdx.x * 4;

        float4 W0 = wp[n0 + 0];
        float4 W1 = wp[n0 + 1];
        float4 W2 = wp[n0 + 2];
        float4 W3 = wp[n0 + 3];

        int j[12];
        {
            unsigned pk0 = __float_as_uint(W0.z);
            unsigned pk1 = __float_as_uint(W1.z);
            unsigned pk2 = __float_as_uint(W2.z);
            unsigned pk3 = __float_as_uint(W3.z);
            j[0]  = pk0 & 0xFFFF; j[1]  = pk0 >> 16; j[2]  = __float_as_uint(W0.w);
            j[3]  = pk1 & 0xFFFF; j[4]  = pk1 >> 16; j[5]  = __float_as_uint(W1.w);
            j[6]  = pk2 & 0xFFFF; j[7]  = pk2 >> 16; j[8]  = __float_as_uint(W2.w);
            j[9]  = pk3 & 0xFFFF; j[10] = pk3 >> 16; j[11] = __float_as_uint(W3.w);
        }

        ulonglong2 f[12];
#pragma unroll
        for (int t = 0; t < 12; t++)
            f[t] = *(const ulonglong2*)&rowsT[j[t] * 4];

        float vq[4][4];
        const float4 Wv[4] = { W0, W1, W2, W3 };
#pragma unroll
        for (int q = 0; q < 4; q++) {
            float w0 = Wv[q].x, w1 = Wv[q].y;
            float w2 = 1.0f - w0 - w1;
            u64t w0p = pack2(w0, w0);
            u64t w1p = pack2(w1, w1);
            u64t w2p = pack2(w2, w2);
            u64t lo = fma2(w0p, f[3*q].x, fma2(w1p, f[3*q+1].x, mul2(w2p, f[3*q+2].x)));
            u64t hi = fma2(w0p, f[3*q].y, fma2(w1p, f[3*q+1].y, mul2(w2p, f[3*q+2].y)));
            unpack2(lo, vq[q][0], vq[q][1]);
            unpack2(hi, vq[q][2], vq[q][3]);
        }

#pragma unroll
        for (int c = 0; c < CG; c++) {
            float4 v = make_float4(vq[0][c], vq[1][c], vq[2][c], vq[3][c]);
            *(float4*)(outp + (size_t)c * NQ + n0) = v;
        }
    }
}

// ---------------------------------------------------------------------------
// Launch
// ---------------------------------------------------------------------------
extern "C" void kernel_launch(void* const* d_in, const int* in_sizes, int n_in,
                              void* d_out, int out_size)
{
    const float* unknown = (const float*)d_in[0];   // (8, 8192, 3)
    const float* known   = (const float*)d_in[1];   // (8, 2048, 3)
    const float* feats   = (const float*)d_in[2];   // (8, 256, 2048)
    float* out = (float*)d_out;                     // (8, 256, 8192)

    bin_kernel<<<dim3(BQ, 2), 512>>>(known, unknown);

    nn_kernel<<<dim3(NCELL / 4, BQ), 128>>>(unknown);

    dim3 g2(CC / CG, BQ);
    interp_kernel<<<g2, 256>>>(feats, out);
}